// round 1
// baseline (speedup 1.0000x reference)
#include <cuda_runtime.h>
#include <cuda_bf16.h>

// YOLO layer: (B, 3*85, 76, 76) fp32 -> (B, 3*76*76, 85) fp32
// Pure HBM-bound transpose + cheap elementwise epilogue.
//
// Per CTA: one (batch b, anchor a, grid-row t) slice = 85 channels x 76 x-positions.
//   Load phase : coalesced reads (76 contiguous floats per channel), transform
//                applied inline, stored to smem[s*85 + k] (stride 85 odd -> no
//                bank conflicts).
//   Store phase: the 76 output rows of 85 floats are CONTIGUOUS in gmem, and
//                smem[j] is already in output order -> linear conflict-free
//                copy, fully coalesced STG.

#define G   76
#define C   85          // 5 + 80 classes
#define NA  3
#define TPB 256
#define TILE (C * G)    // 6460 elements per CTA

__global__ __launch_bounds__(TPB)
void yolo_kernel(const float* __restrict__ in,
                 const void*  __restrict__ imgdim_p,
                 float* __restrict__ out)
{
    __shared__ float tile[TILE];

    const int blk = blockIdx.x;
    const int t   = blk % G;              // grid row (== grid_y)
    const int a   = (blk / G) % NA;       // anchor
    const int b   = blk / (G * NA);       // batch

    // stride = img_dim / g ; scalar input may be int32 or float32 -> sniff bits
    float stride = 8.0f;
    if (imgdim_p) {
        int iv = *(const int*)imgdim_p;
        float dim = (iv > 0 && iv < (1 << 20)) ? (float)iv : __int_as_float(iv);
        stride = dim / (float)G;
    }

    const float AW[NA] = {116.0f, 156.0f, 373.0f};
    const float AH[NA] = { 90.0f, 198.0f, 326.0f};
    // reference: exp(w) * (anchor/stride) * stride — fold to plain anchor,
    // but keep the /stride*stride order-of-ops harmless for rel_err 1e-3.
    const float anchor_w = AW[a];
    const float anchor_h = AH[a];
    const float gy = (float)t;

    const float* base = in + ((size_t)(b * NA + a) * C) * (G * G) + (size_t)t * G;

    #pragma unroll 4
    for (int i = threadIdx.x; i < TILE; i += TPB) {
        const int k = i / G;          // channel 0..84
        const int s = i - k * G;      // x position (== grid_x)
        const float v = __ldg(&base[(size_t)k * (G * G) + s]);
        float r;
        if (k >= 4) {
            r = __fdividef(1.0f, 1.0f + __expf(-v));          // conf / cls
        } else if (k == 0) {
            r = (__fdividef(1.0f, 1.0f + __expf(-v)) + (float)s) * stride;
        } else if (k == 1) {
            r = (__fdividef(1.0f, 1.0f + __expf(-v)) + gy) * stride;
        } else if (k == 2) {
            r = __expf(v) * anchor_w;
        } else { // k == 3
            r = __expf(v) * anchor_h;
        }
        tile[s * C + k] = r;          // stride-85 smem write: conflict-free
    }
    __syncthreads();

    // Output rows for this CTA are contiguous: ((b*NA+a)*G*G + t*G) * C .. +TILE
    float* obase = out + ((size_t)(b * NA + a) * (G * G) + (size_t)t * G) * C;
    #pragma unroll 4
    for (int j = threadIdx.x; j < TILE; j += TPB)
        obase[j] = tile[j];           // linear copy: coalesced, conflict-free
}

extern "C" void kernel_launch(void* const* d_in, const int* in_sizes, int n_in,
                              void* d_out, int out_size)
{
    const float* x = (const float*)d_in[0];
    const void*  dim = (n_in > 1) ? d_in[1] : nullptr;
    const int B = in_sizes[0] / (NA * C * G * G);   // 64 for the bench shape

    dim3 grid(B * NA * G);
    yolo_kernel<<<grid, TPB>>>(x, dim, (float*)d_out);
}

// round 2
// speedup vs baseline: 1.1740x; 1.1740x over previous
#include <cuda_runtime.h>
#include <cuda_bf16.h>
#include <cstdint>

// YOLO layer: (B, 3*85, 76, 76) fp32 -> (B, 3*76*76, 85) fp32
// HBM-bound transpose + elementwise epilogue.
//
// Per CTA: one (batch b, anchor a, grid-row t) slice: 85 channels x 76 cols.
//   Load : float4 LDG (19 vec4 per channel row, rows 16B-aligned), transform,
//          scatter into smem in output order (stride-85 -> conflict-free).
//   Store: single cp.async.bulk shared->global of the whole 25840B tile
//          (already in output layout, dst 16B-aligned) — zero per-element
//          issue cost on the write side.

#define G     76
#define C     85
#define NA    3
#define TPB   256
#define TILE  (C * G)         // 6460 floats
#define TILE4 (TILE / 4)      // 1615 float4 (loads); 85*19 vec4 reads
#define VPC   (G / 4)         // 19 float4 per channel row

__device__ __forceinline__ float sigf(float v) {
    return __fdividef(1.0f, 1.0f + __expf(-v));
}

__global__ __launch_bounds__(TPB)
void yolo_kernel(const float* __restrict__ in,
                 const void*  __restrict__ imgdim_p,
                 float* __restrict__ out)
{
    __shared__ __align__(16) float tile[TILE];

    const int blk = blockIdx.x;
    const int t   = blk % G;              // grid row (grid_y)
    const int a   = (blk / G) % NA;       // anchor
    const int b   = blk / (G * NA);       // batch

    float stride = 8.0f;
    if (imgdim_p) {
        int iv = *(const int*)imgdim_p;
        float dim = (iv > 0 && iv < (1 << 20)) ? (float)iv : __int_as_float(iv);
        stride = dim / (float)G;
    }

    const float AW[NA] = {116.0f, 156.0f, 373.0f};
    const float AH[NA] = { 90.0f, 198.0f, 326.0f};
    const float aw = AW[a], ah = AH[a];
    const float gy = (float)t;

    // input base for this (b,a,t): channel k lives at base + k*G*G, 76 floats
    const float* base = in + ((size_t)(b * NA + a) * C) * (G * G) + (size_t)t * G;

    #pragma unroll 2
    for (unsigned i = threadIdx.x; i < TILE4; i += TPB) {
        const unsigned k = i / VPC;        // channel 0..84
        const unsigned q = i - k * VPC;    // vec4 index within row 0..18
        const float4 v = __ldg((const float4*)(base + (size_t)k * (G * G)) + q);
        const int s0 = q * 4;              // grid_x of component 0

        float r0, r1, r2, r3;
        if (k >= 4) {                      // conf + classes: plain sigmoid
            r0 = sigf(v.x); r1 = sigf(v.y); r2 = sigf(v.z); r3 = sigf(v.w);
        } else if (k == 0) {               // x: (sigmoid + grid_x) * stride
            r0 = (sigf(v.x) + (float)(s0 + 0)) * stride;
            r1 = (sigf(v.y) + (float)(s0 + 1)) * stride;
            r2 = (sigf(v.z) + (float)(s0 + 2)) * stride;
            r3 = (sigf(v.w) + (float)(s0 + 3)) * stride;
        } else if (k == 1) {               // y: (sigmoid + grid_y) * stride
            r0 = (sigf(v.x) + gy) * stride;
            r1 = (sigf(v.y) + gy) * stride;
            r2 = (sigf(v.z) + gy) * stride;
            r3 = (sigf(v.w) + gy) * stride;
        } else if (k == 2) {               // w: exp * anchor_w  (stride folds out)
            r0 = __expf(v.x) * aw; r1 = __expf(v.y) * aw;
            r2 = __expf(v.z) * aw; r3 = __expf(v.w) * aw;
        } else {                           // h: exp * anchor_h
            r0 = __expf(v.x) * ah; r1 = __expf(v.y) * ah;
            r2 = __expf(v.z) * ah; r3 = __expf(v.w) * ah;
        }
        // scatter to output layout: tile[s*C + k]; stride 85 is odd -> conflict-free
        float* p = &tile[(unsigned)s0 * C + k];
        p[0]     = r0;
        p[C]     = r1;
        p[2 * C] = r2;
        p[3 * C] = r3;
    }
    __syncthreads();

    // Bulk async store: tile[] is exactly the 76x85 output block for this CTA,
    // contiguous in gmem. 25840 bytes, 16B-aligned both sides.
    if (threadIdx.x == 0) {
        float* obase = out + ((size_t)(b * NA + a) * (G * G) + (size_t)t * G) * C;
        uint32_t saddr;
        asm("{ .reg .u64 t0; cvta.to.shared.u64 t0, %1; cvt.u32.u64 %0, t0; }"
            : "=r"(saddr) : "l"(tile));
        asm volatile("fence.proxy.async.shared::cta;" ::: "memory");
        asm volatile(
            "cp.async.bulk.global.shared::cta.bulk_group [%0], [%1], %2;"
            :: "l"(obase), "r"(saddr), "n"(TILE * 4) : "memory");
        asm volatile("cp.async.bulk.commit_group;" ::: "memory");
        asm volatile("cp.async.bulk.wait_group 0;" ::: "memory");
    }
}

extern "C" void kernel_launch(void* const* d_in, const int* in_sizes, int n_in,
                              void* d_out, int out_size)
{
    const float* x = (const float*)d_in[0];
    const void*  dim = (n_in > 1) ? d_in[1] : nullptr;
    const int B = in_sizes[0] / (NA * C * G * G);   // 64 for the bench shape

    dim3 grid(B * NA * G);
    yolo_kernel<<<grid, TPB>>>(x, dim, (float*)d_out);
}